// round 13
// baseline (speedup 1.0000x reference)
#include <cuda_runtime.h>
#include <cuda_fp16.h>
#include <math.h>
#include <stdint.h>

// Problem constants
#define BATCH   8
#define SEQ     4096
#define HID     768
#define LINES   256
#define ATTH    1024
#define MTOK    (BATCH*SEQ)      // 32768
#define NPART   8                // 8 N-tiles of 128

#define BM 128
#define BN 128
#define BK 64
#define NKT (HID/BK)             // 12

// ---- scratch (static device globals) ----
__device__ __half g_Xh [(size_t)MTOK * HID];
__device__ __half g_Wt [(size_t)ATTH * HID];   // W1^T [N][K]
__device__ float g_part[MTOK * NPART];

__device__ __forceinline__ float tanh_hw(float x) {
    float y; asm("tanh.approx.f32 %0, %1;" : "=f"(y) : "f"(x)); return y;
}
__device__ __forceinline__ uint32_t smem_u32(const void* p) {
    uint32_t a;
    asm("{ .reg .u64 t; cvta.to.shared.u64 t, %1; cvt.u32.u64 %0, t; }" : "=r"(a) : "l"(p));
    return a;
}
__device__ __forceinline__ void cp16(uint32_t dst, const void* src) {
    asm volatile("cp.async.cg.shared.global [%0], [%1], 16;" :: "r"(dst), "l"(src) : "memory");
}
#define CP_COMMIT()  asm volatile("cp.async.commit_group;" ::: "memory")
#define CP_WAIT(n)   asm volatile("cp.async.wait_group %0;" :: "n"(n) : "memory")

__device__ __forceinline__ void ldm_x4(uint32_t* r, uint32_t addr) {
    asm volatile("ldmatrix.sync.aligned.m8n8.x4.shared.b16 {%0,%1,%2,%3}, [%4];"
                 : "=r"(r[0]), "=r"(r[1]), "=r"(r[2]), "=r"(r[3]) : "r"(addr));
}
__device__ __forceinline__ void mma_f16(float* c, const uint32_t* a, uint32_t b0, uint32_t b1) {
    asm volatile("mma.sync.aligned.m16n8k16.row.col.f32.f16.f16.f32 "
                 "{%0,%1,%2,%3}, {%4,%5,%6,%7}, {%8,%9}, {%0,%1,%2,%3};"
                 : "+f"(c[0]), "+f"(c[1]), "+f"(c[2]), "+f"(c[3])
                 : "r"(a[0]), "r"(a[1]), "r"(a[2]), "r"(a[3]), "r"(b0), "r"(b1));
}

// ---------------------------------------------------------------------------
// Fused conversion kernel.
// Blocks [0, XBLK): X fp32 -> fp16 plane, 8 elems/thread.
// Blocks [XBLK, XBLK+768): W1 [K,N] fp32 -> W1^T [N,K] fp16 (32x32 transpose).
// ---------------------------------------------------------------------------
#define XBLK (MTOK * HID / 8 / 256)   // 12288

__global__ __launch_bounds__(256) void convert_all(
    const float* __restrict__ X, const float* __restrict__ W1)
{
    if (blockIdx.x < XBLK) {
        size_t i8 = (size_t)blockIdx.x * 256 + threadIdx.x;
        float4 v0 = reinterpret_cast<const float4*>(X)[i8 * 2];
        float4 v1 = reinterpret_cast<const float4*>(X)[i8 * 2 + 1];
        __half h[8] = {__float2half_rn(v0.x), __float2half_rn(v0.y),
                       __float2half_rn(v0.z), __float2half_rn(v0.w),
                       __float2half_rn(v1.x), __float2half_rn(v1.y),
                       __float2half_rn(v1.z), __float2half_rn(v1.w)};
        reinterpret_cast<uint4*>(g_Xh)[i8] = *reinterpret_cast<uint4*>(h);
    } else {
        __shared__ float t[32][33];
        int bid = blockIdx.x - XBLK;           // 0..767
        const int n0 = (bid & 31) * 32, k0 = (bid >> 5) * 32;
        const int tx = threadIdx.x & 31, ty = threadIdx.x >> 5;
#pragma unroll
        for (int i = 0; i < 4; i++)
            t[ty + 8 * i][tx] = W1[(size_t)(k0 + ty + 8 * i) * ATTH + n0 + tx];
        __syncthreads();
#pragma unroll
        for (int i = 0; i < 4; i++)
            g_Wt[(size_t)(n0 + ty + 8 * i) * HID + k0 + tx] = __float2half_rn(t[tx][ty + 8 * i]);
    }
}

// ---------------------------------------------------------------------------
// fp16 GEMM via mma.sync + fused epilogue.
// grid (8, 256), 256 threads, 2 CTAs/SM, CTA M128xN128, warp 64x32.
// 3-stage cp.async pipeline, single barrier per ktile, prefetch BEFORE compute.
// ---------------------------------------------------------------------------
#define OFF_A   0
#define OFF_B   16384
#define BUFB    32768
#define NSTAGE  3
#define SMEM_GEMM (NSTAGE*BUFB)   // 98304

__global__ __launch_bounds__(256, 2) void score_gemm_mma(
    const float* __restrict__ b1, const float* __restrict__ W2)
{
    extern __shared__ __align__(128) char smem[];
    const uint32_t sb = smem_u32(smem);
    const int bn = blockIdx.x, bm = blockIdx.y;
    const int tid = threadIdx.x;
    const int lane = tid & 31, wid = tid >> 5;
    const int wid_m = wid >> 2, wid_n = wid & 3;

    const __half* Ah = g_Xh + (size_t)(bm * BM) * HID;
    const __half* Bt = g_Wt + (size_t)(bn * BN) * HID;

    float acc[4][4][4];
#pragma unroll
    for (int i = 0; i < 4; i++)
#pragma unroll
        for (int j = 0; j < 4; j++)
#pragma unroll
            for (int q = 0; q < 4; q++) acc[i][j][q] = 0.f;

    auto issue = [&](int kt) {
        const uint32_t bufb = sb + (kt % NSTAGE) * BUFB;
#pragma unroll
        for (int j = 0; j < 4; j++) {              // A: 1024 x 16B
            int id = tid + 256 * j;
            int r = id >> 3, c8 = id & 7;
            uint32_t o = (uint32_t)(r * 128 + c8 * 16) ^ (uint32_t)((r & 7) << 4);
            cp16(bufb + OFF_A + o, (const char*)(Ah + (size_t)r * HID + kt * BK) + c8 * 16);
        }
#pragma unroll
        for (int j = 0; j < 4; j++) {              // B: 1024 x 16B
            int id = tid + 256 * j;
            int r = id >> 3, c8 = id & 7;
            uint32_t o = (uint32_t)(r * 128 + c8 * 16) ^ (uint32_t)((r & 7) << 4);
            cp16(bufb + OFF_B + o, (const char*)(Bt + (size_t)r * HID + kt * BK) + c8 * 16);
        }
        CP_COMMIT();
    };

    issue(0);
    issue(1);

    for (int kt = 0; kt < NKT; kt++) {
        if (kt + 1 < NKT) { CP_WAIT(1); } else { CP_WAIT(0); }
        __syncthreads();           // single barrier per ktile

        // prefetch FIRST: buffer (kt+2)%3 is free (kt%3 consumed now,
        // (kt+1)%3 in flight) — loads overlap the MMA work below.
        if (kt + 2 < NKT) issue(kt + 2);

        const uint32_t bufb = sb + (kt % NSTAGE) * BUFB;
        const int rrow = lane & 15;
#pragma unroll
        for (int ks = 0; ks < 4; ks++) {
            const int bc = ks * 32 + ((lane >> 4) << 4);
            uint32_t ah[4][4], bq[2][4];
#pragma unroll
            for (int mi = 0; mi < 4; mi++) {
                int ra = wid_m * 64 + mi * 16 + rrow;
                uint32_t o = (uint32_t)(ra * 128 + bc) ^ (uint32_t)((ra & 7) << 4);
                ldm_x4(ah[mi], bufb + OFF_A + o);
            }
#pragma unroll
            for (int g = 0; g < 2; g++) {
                int rb = wid_n * 32 + g * 16 + rrow;
                uint32_t o = (uint32_t)(rb * 128 + bc) ^ (uint32_t)((rb & 7) << 4);
                ldm_x4(bq[g], bufb + OFF_B + o);
            }
#pragma unroll
            for (int mi = 0; mi < 4; mi++) {
#pragma unroll
                for (int ni = 0; ni < 4; ni++) {
                    int g = ni >> 1, hf = ni & 1;
                    mma_f16(acc[mi][ni], ah[mi], bq[g][hf], bq[g][hf + 2]);
                }
            }
        }
    }

    // ---- fused epilogue: tanh(C + b1)*W2, reduce over 128 cols ----
    float bb[4][2], ww[4][2];
#pragma unroll
    for (int ni = 0; ni < 4; ni++) {
        int n = bn * BN + wid_n * 32 + ni * 8 + (lane & 3) * 2;
        bb[ni][0] = b1[n]; bb[ni][1] = b1[n + 1];
        ww[ni][0] = W2[n]; ww[ni][1] = W2[n + 1];
    }
    __syncthreads();   // all compute done before smem reuse as 'red'
    float* red = (float*)smem;   // [128][4]
#pragma unroll
    for (int mi = 0; mi < 4; mi++) {
        float s0 = 0.f, s1 = 0.f;
#pragma unroll
        for (int ni = 0; ni < 4; ni++) {
            s0 += tanh_hw(acc[mi][ni][0] + bb[ni][0]) * ww[ni][0]
                + tanh_hw(acc[mi][ni][1] + bb[ni][1]) * ww[ni][1];
            s1 += tanh_hw(acc[mi][ni][2] + bb[ni][0]) * ww[ni][0]
                + tanh_hw(acc[mi][ni][3] + bb[ni][1]) * ww[ni][1];
        }
        s0 += __shfl_xor_sync(0xffffffffu, s0, 1);
        s0 += __shfl_xor_sync(0xffffffffu, s0, 2);
        s1 += __shfl_xor_sync(0xffffffffu, s1, 1);
        s1 += __shfl_xor_sync(0xffffffffu, s1, 2);
        if ((lane & 3) == 0) {
            int r0 = wid_m * 64 + mi * 16 + (lane >> 2);
            red[(r0)     * 4 + wid_n] = s0;
            red[(r0 + 8) * 4 + wid_n] = s1;
        }
    }
    __syncthreads();
    if (tid < BM) {
        float s = (red[tid * 4 + 0] + red[tid * 4 + 1])
                + (red[tid * 4 + 2] + red[tid * 4 + 3]);
        g_part[(size_t)(bm * BM + tid) * NPART + bn] = s;
    }
}

// ---------------------------------------------------------------------------
// Per-(batch,line) segment softmax + weighted token sum (deterministic).
// line_ids cached in registers across scans.
// ---------------------------------------------------------------------------
__global__ __launch_bounds__(256) void aggregate_kernel(
    const int*   __restrict__ line_ids,
    const float* __restrict__ b2,
    float* __restrict__ out_feats,
    float* __restrict__ out_mask,
    int write_mask)
{
    const int l = blockIdx.x;
    const int b = blockIdx.y;
    const int tid = threadIdx.x;
    const int lane = tid & 31, wrp = tid >> 5;
    const int base = b * SEQ;
    const size_t orow = (size_t)(b * LINES + l) * HID;

    __shared__ float ssum[256];
    __shared__ int   wsum[8];
    __shared__ int   idxs[SEQ];
    __shared__ float wts[SEQ];
    __shared__ float sdenom;

    // scan 1: load line_ids once into registers, count matches
    int lid_reg[SEQ / 256];
    int lcnt = 0;
#pragma unroll
    for (int it = 0; it < SEQ / 256; it++) {
        lid_reg[it] = line_ids[base + tid + 256 * it];
        if (lid_reg[it] == l) lcnt++;
    }

    // warp-inclusive scan of lcnt
    int inc = lcnt;
#pragma unroll
    for (int off = 1; off < 32; off <<= 1) {
        int v = __shfl_up_sync(0xffffffffu, inc, off);
        if (lane >= off) inc += v;
    }
    if (lane == 31) wsum[wrp] = inc;
    __syncthreads();
    int warp_base = 0;
#pragma unroll
    for (int w = 0; w < 8; w++) warp_base += (w < wrp) ? wsum[w] : 0;
    const int cnt = wsum[0] + wsum[1] + wsum[2] + wsum[3]
                  + wsum[4] + wsum[5] + wsum[6] + wsum[7];
    int o = warp_base + inc - lcnt;   // exclusive offset

    if (cnt == 0) {
        for (int c = tid; c < HID; c += 256) out_feats[orow + c] = 0.f;
        if (tid == 0 && write_mask) out_mask[b * LINES + l] = 0.f;
        return;
    }

    // scan 2 (register replay): finalize partials -> score, exp, compact
    const float bias2 = b2[0];
    float lsum = 0.f;
#pragma unroll
    for (int it = 0; it < SEQ / 256; it++) {
        if (lid_reg[it] == l) {
            int s = tid + 256 * it;
            const float4* p = reinterpret_cast<const float4*>(&g_part[(size_t)(base + s) * NPART]);
            float4 v0 = p[0], v1 = p[1];
            float score = ((v0.x + v0.y) + (v0.z + v0.w))
                        + ((v1.x + v1.y) + (v1.z + v1.w)) + bias2;
            float e = __expf(score);        // safe: |score| bounded by ||W2||_1
            idxs[o] = s;
            wts[o]  = e;
            lsum += e;
            o++;
        }
    }
    ssum[tid] = lsum;
    __syncthreads();
#pragma unroll
    for (int off = 128; off > 0; off >>= 1) {
        if (tid < off) ssum[tid] += ssum[tid + off];
        __syncthreads();
    }
    if (tid == 0) sdenom = fmaxf(ssum[0], 1e-20f);
    __syncthreads();

    // weighted sum over fp16 X plane, 4-way unrolled for MLP
    const float inv_denom = 1.0f / sdenom;
    float a0 = 0.f, a1 = 0.f, a2 = 0.f;
    const __half* Xb = g_Xh + (size_t)base * HID;
    int t = 0;
    for (; t + 4 <= cnt; t += 4) {
        const __half* r0 = Xb + (size_t)idxs[t]     * HID;
        const __half* r1 = Xb + (size_t)idxs[t + 1] * HID;
        const __half* r2 = Xb + (size_t)idxs[t + 2] * HID;
        const __half* r3 = Xb + (size_t)idxs[t + 3] * HID;
        float w0 = wts[t], w1 = wts[t + 1], w2 = wts[t + 2], w3 = wts[t + 3];
        float x00 = __half2float(r0[tid]),       x01 = __half2float(r1[tid]);
        float x02 = __half2float(r2[tid]),       x03 = __half2float(r3[tid]);
        float x10 = __half2float(r0[tid + 256]), x11 = __half2float(r1[tid + 256]);
        float x12 = __half2float(r2[tid + 256]), x13 = __half2float(r3[tid + 256]);
        float x20 = __half2float(r0[tid + 512]), x21 = __half2float(r1[tid + 512]);
        float x22 = __half2float(r2[tid + 512]), x23 = __half2float(r3[tid + 512]);
        a0 += w0 * x00 + w1 * x01 + w2 * x02 + w3 * x03;
        a1 += w0 * x10 + w1 * x11 + w2 * x12 + w3 * x13;
        a2 += w0 * x20 + w1 * x21 + w2 * x22 + w3 * x23;
    }
    for (; t < cnt; t++) {
        const __half* row = Xb + (size_t)idxs[t] * HID;
        float w = wts[t];
        a0 += w * __half2float(row[tid]);
        a1 += w * __half2float(row[tid + 256]);
        a2 += w * __half2float(row[tid + 512]);
    }
    out_feats[orow + tid]       = a0 * inv_denom;
    out_feats[orow + tid + 256] = a1 * inv_denom;
    out_feats[orow + tid + 512] = a2 * inv_denom;
    if (tid == 0 && write_mask) out_mask[b * LINES + l] = 1.0f;
}

// ---------------------------------------------------------------------------
extern "C" void kernel_launch(void* const* d_in, const int* in_sizes, int n_in,
                              void* d_out, int out_size)
{
    const float* token_hidden = (const float*)d_in[0];
    const int*   line_ids     = (const int*)  d_in[1];
    const float* W1           = (const float*)d_in[2];
    const float* b1           = (const float*)d_in[3];
    const float* W2           = (const float*)d_in[4];
    const float* b2           = (const float*)d_in[5];

    float* out = (float*)d_out;
    const int feat_elems = BATCH * LINES * HID;
    const int mask_elems = BATCH * LINES;
    int write_mask = (out_size >= feat_elems + mask_elems) ? 1 : 0;
    float* mask_out = write_mask ? (out + feat_elems) : nullptr;

    static int smem_set = 0;
    if (!smem_set) {
        cudaFuncSetAttribute(score_gemm_mma, cudaFuncAttributeMaxDynamicSharedMemorySize, SMEM_GEMM);
        smem_set = 1;
    }

    convert_all<<<XBLK + 768, 256>>>(token_hidden, W1);

    score_gemm_mma<<<dim3(ATTH / BN, MTOK / BM), 256, SMEM_GEMM>>>(b1, W2);

    aggregate_kernel<<<dim3(LINES, BATCH), 256>>>(line_ids, b2,
                                                  out, mask_out, write_mask);
}

// round 14
// speedup vs baseline: 1.0245x; 1.0245x over previous
#include <cuda_runtime.h>
#include <cuda_fp16.h>
#include <math.h>
#include <stdint.h>

// Problem constants
#define BATCH   8
#define SEQ     4096
#define HID     768
#define LINES   256
#define ATTH    1024
#define MTOK    (BATCH*SEQ)      // 32768
#define NPART   8                // 8 N-tiles of 128

#define BM 128
#define BN 128
#define BK 64
#define NKT (HID/BK)             // 12

// ---- scratch (static device globals) ----
__device__ __half g_Xh [(size_t)MTOK * HID];
__device__ __half g_Wt [(size_t)ATTH * HID];   // W1^T [N][K]
__device__ float g_part[MTOK * NPART];

__device__ __forceinline__ float tanh_hw(float x) {
    float y; asm("tanh.approx.f32 %0, %1;" : "=f"(y) : "f"(x)); return y;
}
__device__ __forceinline__ uint32_t smem_u32(const void* p) {
    uint32_t a;
    asm("{ .reg .u64 t; cvta.to.shared.u64 t, %1; cvt.u32.u64 %0, t; }" : "=r"(a) : "l"(p));
    return a;
}
__device__ __forceinline__ void cp16(uint32_t dst, const void* src) {
    asm volatile("cp.async.cg.shared.global [%0], [%1], 16;" :: "r"(dst), "l"(src) : "memory");
}
#define CP_COMMIT()  asm volatile("cp.async.commit_group;" ::: "memory")
#define CP_WAIT(n)   asm volatile("cp.async.wait_group %0;" :: "n"(n) : "memory")

__device__ __forceinline__ void ldm_x4(uint32_t* r, uint32_t addr) {
    asm volatile("ldmatrix.sync.aligned.m8n8.x4.shared.b16 {%0,%1,%2,%3}, [%4];"
                 : "=r"(r[0]), "=r"(r[1]), "=r"(r[2]), "=r"(r[3]) : "r"(addr));
}
__device__ __forceinline__ void mma_f16(float* c, const uint32_t* a, uint32_t b0, uint32_t b1) {
    asm volatile("mma.sync.aligned.m16n8k16.row.col.f32.f16.f16.f32 "
                 "{%0,%1,%2,%3}, {%4,%5,%6,%7}, {%8,%9}, {%0,%1,%2,%3};"
                 : "+f"(c[0]), "+f"(c[1]), "+f"(c[2]), "+f"(c[3])
                 : "r"(a[0]), "r"(a[1]), "r"(a[2]), "r"(a[3]), "r"(b0), "r"(b1));
}

// ---------------------------------------------------------------------------
// Fused conversion kernel.
// Blocks [0, XBLK): X fp32 -> fp16 plane, 8 elems/thread.
// Blocks [XBLK, XBLK+768): W1 [K,N] fp32 -> W1^T [N,K] fp16 (32x32 transpose).
// ---------------------------------------------------------------------------
#define XBLK (MTOK * HID / 8 / 256)   // 12288

__global__ __launch_bounds__(256) void convert_all(
    const float* __restrict__ X, const float* __restrict__ W1)
{
    if (blockIdx.x < XBLK) {
        size_t i8 = (size_t)blockIdx.x * 256 + threadIdx.x;
        float4 v0 = reinterpret_cast<const float4*>(X)[i8 * 2];
        float4 v1 = reinterpret_cast<const float4*>(X)[i8 * 2 + 1];
        __half h[8] = {__float2half_rn(v0.x), __float2half_rn(v0.y),
                       __float2half_rn(v0.z), __float2half_rn(v0.w),
                       __float2half_rn(v1.x), __float2half_rn(v1.y),
                       __float2half_rn(v1.z), __float2half_rn(v1.w)};
        reinterpret_cast<uint4*>(g_Xh)[i8] = *reinterpret_cast<uint4*>(h);
    } else {
        __shared__ float t[32][33];
        int bid = blockIdx.x - XBLK;           // 0..767
        const int n0 = (bid & 31) * 32, k0 = (bid >> 5) * 32;
        const int tx = threadIdx.x & 31, ty = threadIdx.x >> 5;
#pragma unroll
        for (int i = 0; i < 4; i++)
            t[ty + 8 * i][tx] = W1[(size_t)(k0 + ty + 8 * i) * ATTH + n0 + tx];
        __syncthreads();
#pragma unroll
        for (int i = 0; i < 4; i++)
            g_Wt[(size_t)(n0 + ty + 8 * i) * HID + k0 + tx] = __float2half_rn(t[tx][ty + 8 * i]);
    }
}

// ---------------------------------------------------------------------------
// fp16 GEMM via mma.sync + fused epilogue (exact R12 configuration).
// grid (8, 256), 256 threads, 2 CTAs/SM, CTA M128xN128, warp 64x32.
// 3-stage cp.async pipeline, single barrier per ktile, issue AFTER compute.
// ---------------------------------------------------------------------------
#define OFF_A   0
#define OFF_B   16384
#define BUFB    32768
#define NSTAGE  3
#define SMEM_GEMM (NSTAGE*BUFB)   // 98304

__global__ __launch_bounds__(256, 2) void score_gemm_mma(
    const float* __restrict__ b1, const float* __restrict__ W2)
{
    extern __shared__ __align__(128) char smem[];
    const uint32_t sb = smem_u32(smem);
    const int bn = blockIdx.x, bm = blockIdx.y;
    const int tid = threadIdx.x;
    const int lane = tid & 31, wid = tid >> 5;
    const int wid_m = wid >> 2, wid_n = wid & 3;

    const __half* Ah = g_Xh + (size_t)(bm * BM) * HID;
    const __half* Bt = g_Wt + (size_t)(bn * BN) * HID;

    float acc[4][4][4];
#pragma unroll
    for (int i = 0; i < 4; i++)
#pragma unroll
        for (int j = 0; j < 4; j++)
#pragma unroll
            for (int q = 0; q < 4; q++) acc[i][j][q] = 0.f;

    auto issue = [&](int kt) {
        const uint32_t bufb = sb + (kt % NSTAGE) * BUFB;
#pragma unroll
        for (int j = 0; j < 4; j++) {              // A: 1024 x 16B
            int id = tid + 256 * j;
            int r = id >> 3, c8 = id & 7;
            uint32_t o = (uint32_t)(r * 128 + c8 * 16) ^ (uint32_t)((r & 7) << 4);
            cp16(bufb + OFF_A + o, (const char*)(Ah + (size_t)r * HID + kt * BK) + c8 * 16);
        }
#pragma unroll
        for (int j = 0; j < 4; j++) {              // B: 1024 x 16B
            int id = tid + 256 * j;
            int r = id >> 3, c8 = id & 7;
            uint32_t o = (uint32_t)(r * 128 + c8 * 16) ^ (uint32_t)((r & 7) << 4);
            cp16(bufb + OFF_B + o, (const char*)(Bt + (size_t)r * HID + kt * BK) + c8 * 16);
        }
        CP_COMMIT();
    };

    issue(0);
    issue(1);

    for (int kt = 0; kt < NKT; kt++) {
        if (kt + 1 < NKT) { CP_WAIT(1); } else { CP_WAIT(0); }
        __syncthreads();           // single barrier per ktile

        const uint32_t bufb = sb + (kt % NSTAGE) * BUFB;
        const int rrow = lane & 15;
#pragma unroll
        for (int ks = 0; ks < 4; ks++) {
            const int bc = ks * 32 + ((lane >> 4) << 4);
            uint32_t ah[4][4], bq[2][4];
#pragma unroll
            for (int mi = 0; mi < 4; mi++) {
                int ra = wid_m * 64 + mi * 16 + rrow;
                uint32_t o = (uint32_t)(ra * 128 + bc) ^ (uint32_t)((ra & 7) << 4);
                ldm_x4(ah[mi], bufb + OFF_A + o);
            }
#pragma unroll
            for (int g = 0; g < 2; g++) {
                int rb = wid_n * 32 + g * 16 + rrow;
                uint32_t o = (uint32_t)(rb * 128 + bc) ^ (uint32_t)((rb & 7) << 4);
                ldm_x4(bq[g], bufb + OFF_B + o);
            }
#pragma unroll
            for (int mi = 0; mi < 4; mi++) {
#pragma unroll
                for (int ni = 0; ni < 4; ni++) {
                    int g = ni >> 1, hf = ni & 1;
                    mma_f16(acc[mi][ni], ah[mi], bq[g][hf], bq[g][hf + 2]);
                }
            }
        }
        if (kt + 2 < NKT) issue(kt + 2);   // writes (kt+2)%3 != kt%3: no alias
    }

    // ---- fused epilogue: tanh(C + b1)*W2, reduce over 128 cols ----
    float bb[4][2], ww[4][2];
#pragma unroll
    for (int ni = 0; ni < 4; ni++) {
        int n = bn * BN + wid_n * 32 + ni * 8 + (lane & 3) * 2;
        bb[ni][0] = b1[n]; bb[ni][1] = b1[n + 1];
        ww[ni][0] = W2[n]; ww[ni][1] = W2[n + 1];
    }
    __syncthreads();   // all compute done before smem reuse as 'red'
    float* red = (float*)smem;   // [128][4]
#pragma unroll
    for (int mi = 0; mi < 4; mi++) {
        float s0 = 0.f, s1 = 0.f;
#pragma unroll
        for (int ni = 0; ni < 4; ni++) {
            s0 += tanh_hw(acc[mi][ni][0] + bb[ni][0]) * ww[ni][0]
                + tanh_hw(acc[mi][ni][1] + bb[ni][1]) * ww[ni][1];
            s1 += tanh_hw(acc[mi][ni][2] + bb[ni][0]) * ww[ni][0]
                + tanh_hw(acc[mi][ni][3] + bb[ni][1]) * ww[ni][1];
        }
        s0 += __shfl_xor_sync(0xffffffffu, s0, 1);
        s0 += __shfl_xor_sync(0xffffffffu, s0, 2);
        s1 += __shfl_xor_sync(0xffffffffu, s1, 1);
        s1 += __shfl_xor_sync(0xffffffffu, s1, 2);
        if ((lane & 3) == 0) {
            int r0 = wid_m * 64 + mi * 16 + (lane >> 2);
            red[(r0)     * 4 + wid_n] = s0;
            red[(r0 + 8) * 4 + wid_n] = s1;
        }
    }
    __syncthreads();
    if (tid < BM) {
        float s = (red[tid * 4 + 0] + red[tid * 4 + 1])
                + (red[tid * 4 + 2] + red[tid * 4 + 3]);
        g_part[(size_t)(bm * BM + tid) * NPART + bn] = s;
    }
}

// ---------------------------------------------------------------------------
// Per-(batch,line) segment softmax + weighted token sum (deterministic).
// uint16 idxs (26KB smem -> higher occupancy), shuffle-based denominator.
// ---------------------------------------------------------------------------
__global__ __launch_bounds__(256) void aggregate_kernel(
    const int*   __restrict__ line_ids,
    const float* __restrict__ b2,
    float* __restrict__ out_feats,
    float* __restrict__ out_mask,
    int write_mask)
{
    const int l = blockIdx.x;
    const int b = blockIdx.y;
    const int tid = threadIdx.x;
    const int lane = tid & 31, wrp = tid >> 5;
    const int base = b * SEQ;
    const size_t orow = (size_t)(b * LINES + l) * HID;

    __shared__ int            wsum[8];
    __shared__ float          fsum[8];
    __shared__ unsigned short idxs[SEQ];
    __shared__ float          wts[SEQ];
    __shared__ float          sdenom;

    // scan 1: count matches
    int lcnt = 0;
#pragma unroll
    for (int it = 0; it < SEQ / 256; it++) {
        if (line_ids[base + tid + 256 * it] == l) lcnt++;
    }

    // warp-inclusive scan of lcnt
    int inc = lcnt;
#pragma unroll
    for (int off = 1; off < 32; off <<= 1) {
        int v = __shfl_up_sync(0xffffffffu, inc, off);
        if (lane >= off) inc += v;
    }
    if (lane == 31) wsum[wrp] = inc;
    __syncthreads();
    int warp_base = 0;
#pragma unroll
    for (int w = 0; w < 8; w++) warp_base += (w < wrp) ? wsum[w] : 0;
    const int cnt = wsum[0] + wsum[1] + wsum[2] + wsum[3]
                  + wsum[4] + wsum[5] + wsum[6] + wsum[7];
    int o = warp_base + inc - lcnt;   // exclusive offset

    if (cnt == 0) {
        for (int c = tid; c < HID; c += 256) out_feats[orow + c] = 0.f;
        if (tid == 0 && write_mask) out_mask[b * LINES + l] = 0.f;
        return;
    }

    // scan 2: fused finalize (partials -> score), exp, compact, denom accum
    const float bias2 = b2[0];
    float lsum = 0.f;
#pragma unroll
    for (int it = 0; it < SEQ / 256; it++) {
        int s = tid + 256 * it;
        if (line_ids[base + s] == l) {
            const float4* p = reinterpret_cast<const float4*>(&g_part[(size_t)(base + s) * NPART]);
            float4 v0 = p[0], v1 = p[1];
            float score = ((v0.x + v0.y) + (v0.z + v0.w))
                        + ((v1.x + v1.y) + (v1.z + v1.w)) + bias2;
            float e = __expf(score);        // safe: |score| bounded by ||W2||_1
            idxs[o] = (unsigned short)s;
            wts[o]  = e;
            lsum += e;
            o++;
        }
    }
    // warp-shuffle denominator reduction (2 barriers total)
#pragma unroll
    for (int off = 16; off > 0; off >>= 1)
        lsum += __shfl_xor_sync(0xffffffffu, lsum, off);
    if (lane == 0) fsum[wrp] = lsum;
    __syncthreads();
    if (tid == 0) {
        float d = ((fsum[0] + fsum[1]) + (fsum[2] + fsum[3]))
                + ((fsum[4] + fsum[5]) + (fsum[6] + fsum[7]));
        sdenom = fmaxf(d, 1e-20f);
    }
    __syncthreads();

    // weighted sum over fp16 X plane, 4-way unrolled for MLP
    const float inv_denom = 1.0f / sdenom;
    float a0 = 0.f, a1 = 0.f, a2 = 0.f;
    const __half* Xb = g_Xh + (size_t)base * HID;
    int t = 0;
    for (; t + 4 <= cnt; t += 4) {
        const __half* r0 = Xb + (size_t)idxs[t]     * HID;
        const __half* r1 = Xb + (size_t)idxs[t + 1] * HID;
        const __half* r2 = Xb + (size_t)idxs[t + 2] * HID;
        const __half* r3 = Xb + (size_t)idxs[t + 3] * HID;
        float w0 = wts[t], w1 = wts[t + 1], w2 = wts[t + 2], w3 = wts[t + 3];
        float x00 = __half2float(r0[tid]),       x01 = __half2float(r1[tid]);
        float x02 = __half2float(r2[tid]),       x03 = __half2float(r3[tid]);
        float x10 = __half2float(r0[tid + 256]), x11 = __half2float(r1[tid + 256]);
        float x12 = __half2float(r2[tid + 256]), x13 = __half2float(r3[tid + 256]);
        float x20 = __half2float(r0[tid + 512]), x21 = __half2float(r1[tid + 512]);
        float x22 = __half2float(r2[tid + 512]), x23 = __half2float(r3[tid + 512]);
        a0 += w0 * x00 + w1 * x01 + w2 * x02 + w3 * x03;
        a1 += w0 * x10 + w1 * x11 + w2 * x12 + w3 * x13;
        a2 += w0 * x20 + w1 * x21 + w2 * x22 + w3 * x23;
    }
    for (; t < cnt; t++) {
        const __half* row = Xb + (size_t)idxs[t] * HID;
        float w = wts[t];
        a0 += w * __half2float(row[tid]);
        a1 += w * __half2float(row[tid + 256]);
        a2 += w * __half2float(row[tid + 512]);
    }
    out_feats[orow + tid]       = a0 * inv_denom;
    out_feats[orow + tid + 256] = a1 * inv_denom;
    out_feats[orow + tid + 512] = a2 * inv_denom;
    if (tid == 0 && write_mask) out_mask[b * LINES + l] = 1.0f;
}

// ---------------------------------------------------------------------------
extern "C" void kernel_launch(void* const* d_in, const int* in_sizes, int n_in,
                              void* d_out, int out_size)
{
    const float* token_hidden = (const float*)d_in[0];
    const int*   line_ids     = (const int*)  d_in[1];
    const float* W1           = (const float*)d_in[2];
    const float* b1           = (const float*)d_in[3];
    const float* W2           = (const float*)d_in[4];
    const float* b2           = (const float*)d_in[5];

    float* out = (float*)d_out;
    const int feat_elems = BATCH * LINES * HID;
    const int mask_elems = BATCH * LINES;
    int write_mask = (out_size >= feat_elems + mask_elems) ? 1 : 0;
    float* mask_out = write_mask ? (out + feat_elems) : nullptr;

    static int smem_set = 0;
    if (!smem_set) {
        cudaFuncSetAttribute(score_gemm_mma, cudaFuncAttributeMaxDynamicSharedMemorySize, SMEM_GEMM);
        smem_set = 1;
    }

    convert_all<<<XBLK + 768, 256>>>(token_hidden, W1);

    score_gemm_mma<<<dim3(ATTH / BN, MTOK / BM), 256, SMEM_GEMM>>>(b1, W2);

    aggregate_kernel<<<dim3(LINES, BATCH), 256>>>(line_ids, b2,
                                                  out, mask_out, write_mask);
}

// round 15
// speedup vs baseline: 1.0269x; 1.0024x over previous
#include <cuda_runtime.h>
#include <cuda_fp16.h>
#include <math.h>
#include <stdint.h>

// Problem constants
#define BATCH   8
#define SEQ     4096
#define HID     768
#define LINES   256
#define ATTH    1024
#define MTOK    (BATCH*SEQ)      // 32768
#define NPART   8                // 8 N-tiles of 128

#define BM 128
#define BN 128
#define BK 64
#define NKT (HID/BK)             // 12

// ---- scratch (static device globals) ----
__device__ __half g_Xh [(size_t)MTOK * HID];
__device__ __half g_Wt [(size_t)ATTH * HID];   // W1^T [N][K]
__device__ float g_part[MTOK * NPART];

__device__ __forceinline__ float tanh_hw(float x) {
    float y; asm("tanh.approx.f32 %0, %1;" : "=f"(y) : "f"(x)); return y;
}
__device__ __forceinline__ uint32_t smem_u32(const void* p) {
    uint32_t a;
    asm("{ .reg .u64 t; cvta.to.shared.u64 t, %1; cvt.u32.u64 %0, t; }" : "=r"(a) : "l"(p));
    return a;
}
__device__ __forceinline__ void cp16(uint32_t dst, const void* src) {
    asm volatile("cp.async.cg.shared.global [%0], [%1], 16;" :: "r"(dst), "l"(src) : "memory");
}
#define CP_COMMIT()  asm volatile("cp.async.commit_group;" ::: "memory")
#define CP_WAIT(n)   asm volatile("cp.async.wait_group %0;" :: "n"(n) : "memory")

__device__ __forceinline__ void ldm_x4(uint32_t* r, uint32_t addr) {
    asm volatile("ldmatrix.sync.aligned.m8n8.x4.shared.b16 {%0,%1,%2,%3}, [%4];"
                 : "=r"(r[0]), "=r"(r[1]), "=r"(r[2]), "=r"(r[3]) : "r"(addr));
}
__device__ __forceinline__ void mma_f16(float* c, const uint32_t* a, uint32_t b0, uint32_t b1) {
    asm volatile("mma.sync.aligned.m16n8k16.row.col.f32.f16.f16.f32 "
                 "{%0,%1,%2,%3}, {%4,%5,%6,%7}, {%8,%9}, {%0,%1,%2,%3};"
                 : "+f"(c[0]), "+f"(c[1]), "+f"(c[2]), "+f"(c[3])
                 : "r"(a[0]), "r"(a[1]), "r"(a[2]), "r"(a[3]), "r"(b0), "r"(b1));
}

// ---------------------------------------------------------------------------
// Fused conversion kernel.
// Blocks [0, XBLK): X fp32 -> fp16 plane, 8 elems/thread.
// Blocks [XBLK, XBLK+768): W1 [K,N] fp32 -> W1^T [N,K] fp16 (32x32 transpose).
// ---------------------------------------------------------------------------
#define XBLK (MTOK * HID / 8 / 256)   // 12288

__global__ __launch_bounds__(256) void convert_all(
    const float* __restrict__ X, const float* __restrict__ W1)
{
    if (blockIdx.x < XBLK) {
        size_t i8 = (size_t)blockIdx.x * 256 + threadIdx.x;
        float4 v0 = reinterpret_cast<const float4*>(X)[i8 * 2];
        float4 v1 = reinterpret_cast<const float4*>(X)[i8 * 2 + 1];
        __half h[8] = {__float2half_rn(v0.x), __float2half_rn(v0.y),
                       __float2half_rn(v0.z), __float2half_rn(v0.w),
                       __float2half_rn(v1.x), __float2half_rn(v1.y),
                       __float2half_rn(v1.z), __float2half_rn(v1.w)};
        reinterpret_cast<uint4*>(g_Xh)[i8] = *reinterpret_cast<uint4*>(h);
    } else {
        __shared__ float t[32][33];
        int bid = blockIdx.x - XBLK;           // 0..767
        const int n0 = (bid & 31) * 32, k0 = (bid >> 5) * 32;
        const int tx = threadIdx.x & 31, ty = threadIdx.x >> 5;
#pragma unroll
        for (int i = 0; i < 4; i++)
            t[ty + 8 * i][tx] = W1[(size_t)(k0 + ty + 8 * i) * ATTH + n0 + tx];
        __syncthreads();
#pragma unroll
        for (int i = 0; i < 4; i++)
            g_Wt[(size_t)(n0 + ty + 8 * i) * HID + k0 + tx] = __float2half_rn(t[tx][ty + 8 * i]);
    }
}

// ---------------------------------------------------------------------------
// fp16 GEMM via mma.sync + fused epilogue (exact R12 configuration — frozen).
// grid (8, 256), 256 threads, 2 CTAs/SM, CTA M128xN128, warp 64x32.
// 3-stage cp.async pipeline, single barrier per ktile, issue AFTER compute.
// ---------------------------------------------------------------------------
#define OFF_A   0
#define OFF_B   16384
#define BUFB    32768
#define NSTAGE  3
#define SMEM_GEMM (NSTAGE*BUFB)   // 98304

__global__ __launch_bounds__(256, 2) void score_gemm_mma(
    const float* __restrict__ b1, const float* __restrict__ W2)
{
    extern __shared__ __align__(128) char smem[];
    const uint32_t sb = smem_u32(smem);
    const int bn = blockIdx.x, bm = blockIdx.y;
    const int tid = threadIdx.x;
    const int lane = tid & 31, wid = tid >> 5;
    const int wid_m = wid >> 2, wid_n = wid & 3;

    const __half* Ah = g_Xh + (size_t)(bm * BM) * HID;
    const __half* Bt = g_Wt + (size_t)(bn * BN) * HID;

    float acc[4][4][4];
#pragma unroll
    for (int i = 0; i < 4; i++)
#pragma unroll
        for (int j = 0; j < 4; j++)
#pragma unroll
            for (int q = 0; q < 4; q++) acc[i][j][q] = 0.f;

    auto issue = [&](int kt) {
        const uint32_t bufb = sb + (kt % NSTAGE) * BUFB;
#pragma unroll
        for (int j = 0; j < 4; j++) {              // A: 1024 x 16B
            int id = tid + 256 * j;
            int r = id >> 3, c8 = id & 7;
            uint32_t o = (uint32_t)(r * 128 + c8 * 16) ^ (uint32_t)((r & 7) << 4);
            cp16(bufb + OFF_A + o, (const char*)(Ah + (size_t)r * HID + kt * BK) + c8 * 16);
        }
#pragma unroll
        for (int j = 0; j < 4; j++) {              // B: 1024 x 16B
            int id = tid + 256 * j;
            int r = id >> 3, c8 = id & 7;
            uint32_t o = (uint32_t)(r * 128 + c8 * 16) ^ (uint32_t)((r & 7) << 4);
            cp16(bufb + OFF_B + o, (const char*)(Bt + (size_t)r * HID + kt * BK) + c8 * 16);
        }
        CP_COMMIT();
    };

    issue(0);
    issue(1);

    for (int kt = 0; kt < NKT; kt++) {
        if (kt + 1 < NKT) { CP_WAIT(1); } else { CP_WAIT(0); }
        __syncthreads();           // single barrier per ktile

        const uint32_t bufb = sb + (kt % NSTAGE) * BUFB;
        const int rrow = lane & 15;
#pragma unroll
        for (int ks = 0; ks < 4; ks++) {
            const int bc = ks * 32 + ((lane >> 4) << 4);
            uint32_t ah[4][4], bq[2][4];
#pragma unroll
            for (int mi = 0; mi < 4; mi++) {
                int ra = wid_m * 64 + mi * 16 + rrow;
                uint32_t o = (uint32_t)(ra * 128 + bc) ^ (uint32_t)((ra & 7) << 4);
                ldm_x4(ah[mi], bufb + OFF_A + o);
            }
#pragma unroll
            for (int g = 0; g < 2; g++) {
                int rb = wid_n * 32 + g * 16 + rrow;
                uint32_t o = (uint32_t)(rb * 128 + bc) ^ (uint32_t)((rb & 7) << 4);
                ldm_x4(bq[g], bufb + OFF_B + o);
            }
#pragma unroll
            for (int mi = 0; mi < 4; mi++) {
#pragma unroll
                for (int ni = 0; ni < 4; ni++) {
                    int g = ni >> 1, hf = ni & 1;
                    mma_f16(acc[mi][ni], ah[mi], bq[g][hf], bq[g][hf + 2]);
                }
            }
        }
        if (kt + 2 < NKT) issue(kt + 2);   // writes (kt+2)%3 != kt%3: no alias
    }

    // ---- fused epilogue: tanh(C + b1)*W2, reduce over 128 cols ----
    float bb[4][2], ww[4][2];
#pragma unroll
    for (int ni = 0; ni < 4; ni++) {
        int n = bn * BN + wid_n * 32 + ni * 8 + (lane & 3) * 2;
        bb[ni][0] = b1[n]; bb[ni][1] = b1[n + 1];
        ww[ni][0] = W2[n]; ww[ni][1] = W2[n + 1];
    }
    __syncthreads();   // all compute done before smem reuse as 'red'
    float* red = (float*)smem;   // [128][4]
#pragma unroll
    for (int mi = 0; mi < 4; mi++) {
        float s0 = 0.f, s1 = 0.f;
#pragma unroll
        for (int ni = 0; ni < 4; ni++) {
            s0 += tanh_hw(acc[mi][ni][0] + bb[ni][0]) * ww[ni][0]
                + tanh_hw(acc[mi][ni][1] + bb[ni][1]) * ww[ni][1];
            s1 += tanh_hw(acc[mi][ni][2] + bb[ni][0]) * ww[ni][0]
                + tanh_hw(acc[mi][ni][3] + bb[ni][1]) * ww[ni][1];
        }
        s0 += __shfl_xor_sync(0xffffffffu, s0, 1);
        s0 += __shfl_xor_sync(0xffffffffu, s0, 2);
        s1 += __shfl_xor_sync(0xffffffffu, s1, 1);
        s1 += __shfl_xor_sync(0xffffffffu, s1, 2);
        if ((lane & 3) == 0) {
            int r0 = wid_m * 64 + mi * 16 + (lane >> 2);
            red[(r0)     * 4 + wid_n] = s0;
            red[(r0 + 8) * 4 + wid_n] = s1;
        }
    }
    __syncthreads();
    if (tid < BM) {
        float s = (red[tid * 4 + 0] + red[tid * 4 + 1])
                + (red[tid * 4 + 2] + red[tid * 4 + 3]);
        g_part[(size_t)(bm * BM + tid) * NPART + bn] = s;
    }
}

// ---------------------------------------------------------------------------
// Per-(batch,line) segment softmax + weighted token sum (deterministic).
// int4-vectorized line_ids scan, cached in registers across both scans.
// Thread t owns tokens s = (t + 256*it)*4 + j, j in [0,4) — ascending per
// thread, so prefix-scan compaction stays deterministic.
// ---------------------------------------------------------------------------
__global__ __launch_bounds__(256) void aggregate_kernel(
    const int*   __restrict__ line_ids,
    const float* __restrict__ b2,
    float* __restrict__ out_feats,
    float* __restrict__ out_mask,
    int write_mask)
{
    const int l = blockIdx.x;
    const int b = blockIdx.y;
    const int tid = threadIdx.x;
    const int lane = tid & 31, wrp = tid >> 5;
    const int base = b * SEQ;
    const size_t orow = (size_t)(b * LINES + l) * HID;

    __shared__ int            wsum[8];
    __shared__ float          fsum[8];
    __shared__ unsigned short idxs[SEQ];
    __shared__ float          wts[SEQ];
    __shared__ float          sdenom;

    // scan 1: vectorized load of line_ids (4 x LDG.128/thread), cached
    const int4* L4 = reinterpret_cast<const int4*>(line_ids + base);
    int4 lv[SEQ / 1024];          // 4 int4 = 16 ids per thread
    int lcnt = 0;
#pragma unroll
    for (int it = 0; it < SEQ / 1024; it++) {
        lv[it] = L4[tid + 256 * it];
        lcnt += (lv[it].x == l) + (lv[it].y == l) + (lv[it].z == l) + (lv[it].w == l);
    }

    // warp-inclusive scan of lcnt
    int inc = lcnt;
#pragma unroll
    for (int off = 1; off < 32; off <<= 1) {
        int v = __shfl_up_sync(0xffffffffu, inc, off);
        if (lane >= off) inc += v;
    }
    if (lane == 31) wsum[wrp] = inc;
    __syncthreads();
    int warp_base = 0;
#pragma unroll
    for (int w = 0; w < 8; w++) warp_base += (w < wrp) ? wsum[w] : 0;
    const int cnt = wsum[0] + wsum[1] + wsum[2] + wsum[3]
                  + wsum[4] + wsum[5] + wsum[6] + wsum[7];
    int o = warp_base + inc - lcnt;   // exclusive offset

    if (cnt == 0) {
        for (int c = tid; c < HID; c += 256) out_feats[orow + c] = 0.f;
        if (tid == 0 && write_mask) out_mask[b * LINES + l] = 0.f;
        return;
    }

    // scan 2 (register replay): finalize partials -> score, exp, compact
    const float bias2 = b2[0];
    float lsum = 0.f;
#pragma unroll
    for (int it = 0; it < SEQ / 1024; it++) {
        int m4[4] = {lv[it].x, lv[it].y, lv[it].z, lv[it].w};
        int s0 = (tid + 256 * it) * 4;
#pragma unroll
        for (int j = 0; j < 4; j++) {
            if (m4[j] == l) {
                int s = s0 + j;
                const float4* p = reinterpret_cast<const float4*>(&g_part[(size_t)(base + s) * NPART]);
                float4 v0 = p[0], v1 = p[1];
                float score = ((v0.x + v0.y) + (v0.z + v0.w))
                            + ((v1.x + v1.y) + (v1.z + v1.w)) + bias2;
                float e = __expf(score);    // safe: |score| bounded by ||W2||_1
                idxs[o] = (unsigned short)s;
                wts[o]  = e;
                lsum += e;
                o++;
            }
        }
    }
    // warp-shuffle denominator reduction (2 barriers total)
#pragma unroll
    for (int off = 16; off > 0; off >>= 1)
        lsum += __shfl_xor_sync(0xffffffffu, lsum, off);
    if (lane == 0) fsum[wrp] = lsum;
    __syncthreads();
    if (tid == 0) {
        float d = ((fsum[0] + fsum[1]) + (fsum[2] + fsum[3]))
                + ((fsum[4] + fsum[5]) + (fsum[6] + fsum[7]));
        sdenom = fmaxf(d, 1e-20f);
    }
    __syncthreads();

    // weighted sum over fp16 X plane, 4-way unrolled for MLP
    const float inv_denom = 1.0f / sdenom;
    float a0 = 0.f, a1 = 0.f, a2 = 0.f;
    const __half* Xb = g_Xh + (size_t)base * HID;
    int t = 0;
    for (; t + 4 <= cnt; t += 4) {
        const __half* r0 = Xb + (size_t)idxs[t]     * HID;
        const __half* r1 = Xb + (size_t)idxs[t + 1] * HID;
        const __half* r2 = Xb + (size_t)idxs[t + 2] * HID;
        const __half* r3 = Xb + (size_t)idxs[t + 3] * HID;
        float w0 = wts[t], w1 = wts[t + 1], w2 = wts[t + 2], w3 = wts[t + 3];
        float x00 = __half2float(r0[tid]),       x01 = __half2float(r1[tid]);
        float x02 = __half2float(r2[tid]),       x03 = __half2float(r3[tid]);
        float x10 = __half2float(r0[tid + 256]), x11 = __half2float(r1[tid + 256]);
        float x12 = __half2float(r2[tid + 256]), x13 = __half2float(r3[tid + 256]);
        float x20 = __half2float(r0[tid + 512]), x21 = __half2float(r1[tid + 512]);
        float x22 = __half2float(r2[tid + 512]), x23 = __half2float(r3[tid + 512]);
        a0 += w0 * x00 + w1 * x01 + w2 * x02 + w3 * x03;
        a1 += w0 * x10 + w1 * x11 + w2 * x12 + w3 * x13;
        a2 += w0 * x20 + w1 * x21 + w2 * x22 + w3 * x23;
    }
    for (; t < cnt; t++) {
        const __half* row = Xb + (size_t)idxs[t] * HID;
        float w = wts[t];
        a0 += w * __half2float(row[tid]);
        a1 += w * __half2float(row[tid + 256]);
        a2 += w * __half2float(row[tid + 512]);
    }
    out_feats[orow + tid]       = a0 * inv_denom;
    out_feats[orow + tid + 256] = a1 * inv_denom;
    out_feats[orow + tid + 512] = a2 * inv_denom;
    if (tid == 0 && write_mask) out_mask[b * LINES + l] = 1.0f;
}

// ---------------------------------------------------------------------------
extern "C" void kernel_launch(void* const* d_in, const int* in_sizes, int n_in,
                              void* d_out, int out_size)
{
    const float* token_hidden = (const float*)d_in[0];
    const int*   line_ids     = (const int*)  d_in[1];
    const float* W1           = (const float*)d_in[2];
    const float* b1           = (const float*)d_in[3];
    const float* W2           = (const float*)d_in[4];
    const float* b2           = (const float*)d_in[5];

    float* out = (float*)d_out;
    const int feat_elems = BATCH * LINES * HID;
    const int mask_elems = BATCH * LINES;
    int write_mask = (out_size >= feat_elems + mask_elems) ? 1 : 0;
    float* mask_out = write_mask ? (out + feat_elems) : nullptr;

    static int smem_set = 0;
    if (!smem_set) {
        cudaFuncSetAttribute(score_gemm_mma, cudaFuncAttributeMaxDynamicSharedMemorySize, SMEM_GEMM);
        smem_set = 1;
    }

    convert_all<<<XBLK + 768, 256>>>(token_hidden, W1);

    score_gemm_mma<<<dim3(ATTH / BN, MTOK / BM), 256, SMEM_GEMM>>>(b1, W2);

    aggregate_kernel<<<dim3(LINES, BATCH), 256>>>(line_ids, b2,
                                                  out, mask_out, write_mask);
}